// round 11
// baseline (speedup 1.0000x reference)
#include <cuda_runtime.h>
#include <cuda_bf16.h>
#include <cstdint>

#define BATCH 8
#define NT    1024
typedef unsigned long long ull;
typedef unsigned int u32;

// ---------------- scratch (__device__ globals; no allocation allowed) ------
__device__ __align__(16) float g_bufA[BATCH * NT * 256];
__device__ __align__(16) float g_bufB[BATCH * NT * 256];
// packed source scores (s, Es, Es2, 0) and dest scores (d, Ed, Ed2, 0), [h][b][node]
__device__ __align__(16) float4 g_spk[4 * BATCH * NT];
__device__ __align__(16) float4 g_dpk[4 * BATCH * NT];
// pre-transposed bf16-split features [h][b][c=64][node=1024]
__device__ __align__(16) __nv_bfloat16 g_hThi[4 * BATCH * 64 * NT];
__device__ __align__(16) __nv_bfloat16 g_hTlo[4 * BATCH * 64 * NT];
__device__ __align__(16) u32   g_bits[BATCH * NT * (NT / 32)];
__device__ __align__(16) float g_gsum[BATCH * 64];
__device__ __align__(16) float g_z2[BATCH];

// ---------------- helpers --------------------------------------------------
__device__ __forceinline__ uint32_t smem_u32(const void* p) {
    uint32_t a;
    asm("{ .reg .u64 t; cvta.to.shared.u64 t, %1; cvt.u32.u64 %0, t; }" : "=r"(a) : "l"(p));
    return a;
}

__device__ __forceinline__ void ldsm4(u32* r, u32 addr) {
    asm volatile("ldmatrix.sync.aligned.m8n8.x4.shared.b16 {%0,%1,%2,%3}, [%4];"
                 : "=r"(r[0]), "=r"(r[1]), "=r"(r[2]), "=r"(r[3]) : "r"(addr));
}

__device__ __forceinline__ void mma16816(float* c, const u32* a, u32 b0, u32 b1) {
    asm volatile(
        "mma.sync.aligned.m16n8k16.row.col.f32.bf16.bf16.f32 "
        "{%0,%1,%2,%3}, {%4,%5,%6,%7}, {%8,%9}, {%0,%1,%2,%3};"
        : "+f"(c[0]), "+f"(c[1]), "+f"(c[2]), "+f"(c[3])
        : "r"(a[0]), "r"(a[1]), "r"(a[2]), "r"(a[3]), "r"(b0), "r"(b1));
}

// e_ij = adjbit * ( s_j + d_i > 0 ? Es_j*Ed_i : Es2_j*Ed2_i )
__device__ __forceinline__ float edgef(float4 p, float4 dp, u32 bit) {
    float e = (p.x + dp.x > 0.f) ? p.y * dp.y : p.z * dp.z;
    return bit ? e : 0.f;
}

// pack two fp32 into bf16x2 (lower = ex, upper = ey) in one cvt
__device__ __forceinline__ u32 packbf2(float ex, float ey) {
    u32 r;
    asm("cvt.rn.bf16x2.f32 %0, %1, %2;" : "=r"(r) : "f"(ey), "f"(ex));
    return r;
}

// hi/lo bf16 split of a pair, packed
__device__ __forceinline__ void split2(float x0, float x1, u32& hi, u32& lo) {
    hi = packbf2(x0, x1);
    float r0 = x0 - __uint_as_float(hi << 16);
    float r1 = x1 - __uint_as_float(hi & 0xffff0000u);
    lo = packbf2(r0, r1);
}

__device__ __forceinline__ unsigned short bf16of(float x) {
    u32 r = packbf2(x, 0.f);
    return (unsigned short)(r & 0xffffu);
}
__device__ __forceinline__ float bf16res(float x, unsigned short h) {
    return x - __uint_as_float((u32)h << 16);
}

__device__ __forceinline__ u32 swzf(u32 off) { return off ^ ((off >> 3) & 0x70); }

__device__ __forceinline__ void cpasync16(u32 dst, const void* src) {
    asm volatile("cp.async.cg.shared.global [%0], [%1], 16;" :: "r"(dst), "l"(src) : "memory");
}
#define CP_COMMIT() asm volatile("cp.async.commit_group;" ::: "memory")
#define CP_WAIT(n)  asm volatile("cp.async.wait_group %0;" :: "n"(n) : "memory")

#define ONES2 0x3F803F80u   // two bf16 1.0

// ---------------- adj bit packing (with self loops) ------------------------
__global__ void pack_adj_kernel(const int* __restrict__ adj, u32* __restrict__ bits) {
    int row = blockIdx.x;                 // b*NT + i
    int lane = threadIdx.x;               // 32 threads
    int i = row & (NT - 1);
    const int* arow = adj + (size_t)row * NT;
    for (int w = 0; w < 32; w++) {
        int j = w * 32 + lane;
        int v = arow[j];
        unsigned m = __ballot_sync(0xffffffffu, (v > 0) || (j == i));
        if (lane == 0) bits[row * 32 + w] = m;
    }
}

// ---------------- fused HMMA feature GEMM + scores + split-transpose -------
#define TPAD 136
__global__ __launch_bounds__(256) void gemm_fused(
    const float* __restrict__ X, const float* __restrict__ W,
    const float* __restrict__ a_src, const float* __restrict__ a_dst,
    float4* __restrict__ spk, float4* __restrict__ dpk,
    __nv_bfloat16* __restrict__ hhi, __nv_bfloat16* __restrict__ hlo,
    int K)
{
    __shared__ __align__(128) char smbuf[49152];
    __nv_bfloat16* sXh = (__nv_bfloat16*)(smbuf);
    __nv_bfloat16* sXl = (__nv_bfloat16*)(smbuf + 16384);
    __nv_bfloat16* sWh = (__nv_bfloat16*)(smbuf + 32768);
    __nv_bfloat16* sWl = (__nv_bfloat16*)(smbuf + 40960);

    const int tid = threadIdx.x;
    const int w = tid >> 5, l = tid & 31;
    const int h = blockIdx.y;
    const int m0 = blockIdx.x * 128, n0 = h * 64;

    const u32 uXh = smem_u32(sXh), uXl = smem_u32(sXl);
    const u32 uWh = smem_u32(sWh), uWl = smem_u32(sWl);

    float acc[8][4];
#pragma unroll
    for (int ng = 0; ng < 8; ng++)
#pragma unroll
        for (int r = 0; r < 4; r++) acc[ng][r] = 0.f;

    const int arow = w * 16 + (l & 7) + ((l >> 3) & 1) * 8;
    const int akh  = (l >> 4);
    const int sub = l >> 3;
    const int brow = (l & 7) + ((sub >> 1) << 3);

    for (int k0 = 0; k0 < K; k0 += 64) {
        __syncthreads();
#pragma unroll
        for (int i = 0; i < 4; i++) {
            int c = tid + i * 256;
            int row = c >> 3, kg = c & 7;
            const float* p = X + (size_t)(m0 + row) * K + k0 + kg * 8;
            float4 v0 = *(const float4*)p;
            float4 v1 = *(const float4*)(p + 4);
            u32 h0, h1, h2, h3, l0, l1, l2, l3;
            split2(v0.x, v0.y, h0, l0); split2(v0.z, v0.w, h1, l1);
            split2(v1.x, v1.y, h2, l2); split2(v1.z, v1.w, h3, l3);
            u32 off = swzf((u32)(row * 128 + kg * 16));
            *(uint4*)((char*)sXh + off) = make_uint4(h0, h1, h2, h3);
            *(uint4*)((char*)sXl + off) = make_uint4(l0, l1, l2, l3);
        }
#pragma unroll
        for (int i = 0; i < 2; i++) {
            int c = tid + i * 256;
            int row = c >> 3, kg = c & 7;
            const float* p = W + (size_t)(n0 + row) * K + k0 + kg * 8;
            float4 v0 = *(const float4*)p;
            float4 v1 = *(const float4*)(p + 4);
            u32 h0, h1, h2, h3, l0, l1, l2, l3;
            split2(v0.x, v0.y, h0, l0); split2(v0.z, v0.w, h1, l1);
            split2(v1.x, v1.y, h2, l2); split2(v1.z, v1.w, h3, l3);
            u32 off = swzf((u32)(row * 128 + kg * 16));
            *(uint4*)((char*)sWh + off) = make_uint4(h0, h1, h2, h3);
            *(uint4*)((char*)sWl + off) = make_uint4(l0, l1, l2, l3);
        }
        __syncthreads();

#pragma unroll
        for (int q = 0; q < 4; q++) {
            u32 ah[4], al[4];
            u32 aoff = swzf((u32)(arow * 128 + q * 32 + akh * 16));
            ldsm4(ah, uXh + aoff);
            ldsm4(al, uXl + aoff);
            const int bchunk = 2 * q + (sub & 1);
            u32 bh[16], bl[16];
#pragma unroll
            for (int g = 0; g < 4; g++) {
                u32 off = swzf((u32)((g * 16 + brow) * 128 + bchunk * 16));
                ldsm4(bh + g * 4, uWh + off);
                ldsm4(bl + g * 4, uWl + off);
            }
#pragma unroll
            for (int g = 0; g < 4; g++) {
#pragma unroll
                for (int m = 0; m < 2; m++) {
                    int ng = g * 2 + m;
                    u32 b0 = bh[g * 4 + 2 * m], b1 = bh[g * 4 + 2 * m + 1];
                    u32 c0 = bl[g * 4 + 2 * m], c1 = bl[g * 4 + 2 * m + 1];
                    mma16816(acc[ng], ah, b0, b1);
                    mma16816(acc[ng], ah, c0, c1);
                    mma16816(acc[ng], al, b0, b1);
                }
            }
        }
    }

    const int r0 = w * 16 + (l >> 2);
    const int r1 = r0 + 8;

    // ---- epilogue 1: attention scores (4-lane reduce) ----
    {
        float s0 = 0.f, d0 = 0.f, s1 = 0.f, d1 = 0.f;
#pragma unroll
        for (int ng = 0; ng < 8; ng++) {
            int col = ng * 8 + 2 * (l & 3);
            float2 av = *(const float2*)(a_src + n0 + col);
            float2 dv = *(const float2*)(a_dst + n0 + col);
            s0 += acc[ng][0] * av.x + acc[ng][1] * av.y;
            d0 += acc[ng][0] * dv.x + acc[ng][1] * dv.y;
            s1 += acc[ng][2] * av.x + acc[ng][3] * av.y;
            d1 += acc[ng][2] * dv.x + acc[ng][3] * dv.y;
        }
        s0 += __shfl_xor_sync(0xffffffffu, s0, 1);
        s0 += __shfl_xor_sync(0xffffffffu, s0, 2);
        d0 += __shfl_xor_sync(0xffffffffu, d0, 1);
        d0 += __shfl_xor_sync(0xffffffffu, d0, 2);
        s1 += __shfl_xor_sync(0xffffffffu, s1, 1);
        s1 += __shfl_xor_sync(0xffffffffu, s1, 2);
        d1 += __shfl_xor_sync(0xffffffffu, d1, 1);
        d1 += __shfl_xor_sync(0xffffffffu, d1, 2);
        if ((l & 3) == 0) {
            int idx0 = h * (BATCH * NT) + m0 + r0;
            int idx1 = h * (BATCH * NT) + m0 + r1;
            spk[idx0] = make_float4(s0, __expf(s0), __expf(0.2f * s0), 0.f);
            dpk[idx0] = make_float4(d0, __expf(d0), __expf(0.2f * d0), 0.f);
            spk[idx1] = make_float4(s1, __expf(s1), __expf(0.2f * s1), 0.f);
            dpk[idx1] = make_float4(d1, __expf(d1), __expf(0.2f * d1), 0.f);
        }
    }

    // ---- epilogue 2: bf16 hi/lo split + transpose via smem bounce ----
    __syncthreads();
    unsigned short* Th = (unsigned short*)(smbuf);            // [64][TPAD]
    unsigned short* Tl = (unsigned short*)(smbuf + 64 * TPAD * 2);
#pragma unroll
    for (int ng = 0; ng < 8; ng++) {
        int col = ng * 8 + 2 * (l & 3);
#pragma unroll
        for (int v = 0; v < 4; v++) {
            int cc = col + (v & 1);
            int node = (v < 2) ? r0 : r1;
            float x = acc[ng][v];
            unsigned short hb = bf16of(x);
            float res = bf16res(x, hb);
            Th[cc * TPAD + node] = hb;
            Tl[cc * TPAD + node] = bf16of(res);
        }
    }
    __syncthreads();

    const int b = m0 >> 10;
    const int node0 = m0 & (NT - 1);
    const size_t gbase = ((size_t)((h * BATCH + b) * 64)) * NT + node0;
    {
        int c = tid >> 2;
#pragma unroll
        for (int i = 0; i < 4; i++) {
            int nch = (tid & 3) + 4 * i;
            uint4 vh = *(const uint4*)(Th + c * TPAD + nch * 8);
            uint4 vl = *(const uint4*)(Tl + c * TPAD + nch * 8);
            *(uint4*)(hhi + gbase + (size_t)c * NT + nch * 8) = vh;
            *(uint4*)(hlo + gbase + (size_t)c * NT + nch * 8) = vl;
        }
    }
}

// ---------------- HMMA aggregation -----------------------------------------
// grid (NT/128, H, B), 256 threads = 8 warps; warp w owns rows w*16..w*16+15.
// cp.async 3-stage ring staging; scores packed float4; rowsum via ones-B MMA.
// smem layout: buf b: hi @ b*16384, lo @ b*16384+8192; spk @ 49152 + b*1024.
#define AGG_SMEM (49152 + 3 * 1024)
__global__ __launch_bounds__(256, 3) void agg_mma_kernel(
    const __nv_bfloat16* __restrict__ hThi, const __nv_bfloat16* __restrict__ hTlo,
    const float4* __restrict__ spkA, const float4* __restrict__ dpkA,
    const ull* __restrict__ bits64,
    const float* __restrict__ bias, float* __restrict__ xout, int H)
{
    extern __shared__ __align__(128) char smem[];
    const u32 sb = smem_u32(smem);

    const int tid = threadIdx.x;
    const int w = tid >> 5, l = tid & 31;
    const int b = blockIdx.z, h = blockIdx.y;
    const int i0 = blockIdx.x * 128;
    const int hb = h * BATCH + b;
    const int fs = H * 64;

    const int r0 = w * 16 + (l >> 2);
    const int r1 = r0 + 8;
    const float4 dp0 = dpkA[hb * NT + i0 + r0];
    const float4 dp1 = dpkA[hb * NT + i0 + r1];
    const ull* mrow0 = bits64 + (size_t)(b * NT + i0 + r0) * 16;
    const ull* mrow1 = bits64 + (size_t)(b * NT + i0 + r1) * 16;

    const float4* spkp = spkA + hb * NT;
    const __nv_bfloat16* hhp = hThi + (size_t)hb * 64 * NT;
    const __nv_bfloat16* hlp = hTlo + (size_t)hb * 64 * NT;

    const int c0 = tid >> 3, jc = tid & 7;
    const u32 st0 = swzf((u32)(c0 * 128 + jc * 16));
    const u32 st1 = swzf((u32)((c0 + 32) * 128 + jc * 16));

    float acc[8][4];
#pragma unroll
    for (int ng = 0; ng < 8; ng++)
#pragma unroll
        for (int r = 0; r < 4; r++) acc[ng][r] = 0.f;
    float accrs[4] = {0.f, 0.f, 0.f, 0.f};

    auto issue = [&](int t) {
        int j0 = t * 64;
        int buf = t % 3;
        u32 hibase = sb + buf * 16384;
        cpasync16(hibase + st0, hhp + (size_t)c0 * NT + j0 + jc * 8);
        cpasync16(hibase + st1, hhp + (size_t)(c0 + 32) * NT + j0 + jc * 8);
        cpasync16(hibase + 8192 + st0, hlp + (size_t)c0 * NT + j0 + jc * 8);
        cpasync16(hibase + 8192 + st1, hlp + (size_t)(c0 + 32) * NT + j0 + jc * 8);
        if (tid < 64)
            cpasync16(sb + 49152 + buf * 1024 + tid * 16, spkp + j0 + tid);
        CP_COMMIT();
    };

    issue(0);
    issue(1);

    const int sub = l >> 3;
    const int brow = (l & 7) + ((sub >> 1) << 3);

    for (int t = 0; t < 16; t++) {
        if (t == 15) { CP_WAIT(0); } else { CP_WAIT(1); }
        __syncthreads();
        if (t + 2 < 16) issue(t + 2);

        int buf = t % 3;
        const u32 su_hi = sb + buf * 16384;
        const u32 su_lo = su_hi + 8192;
        const float4* sp = (const float4*)(smem + 49152 + buf * 1024);
        const ull m0 = mrow0[t];
        const ull m1 = mrow1[t];

#pragma unroll
        for (int q = 0; q < 4; q++) {
            const int jA = q * 16 + 2 * (l & 3);
            float4 p0 = sp[jA], p1 = sp[jA + 1], p2 = sp[jA + 8], p3 = sp[jA + 9];

            u32 ahi[4];
            // row r0
            {
                float eA = edgef(p0, dp0, (u32)(m0 >> jA) & 1u);
                float eB = edgef(p1, dp0, (u32)(m0 >> (jA + 1)) & 1u);
                float eC = edgef(p2, dp0, (u32)(m0 >> (jA + 8)) & 1u);
                float eD = edgef(p3, dp0, (u32)(m0 >> (jA + 9)) & 1u);
                ahi[0] = packbf2(eA, eB);
                ahi[2] = packbf2(eC, eD);
            }
            // row r1
            {
                float eA = edgef(p0, dp1, (u32)(m1 >> jA) & 1u);
                float eB = edgef(p1, dp1, (u32)(m1 >> (jA + 1)) & 1u);
                float eC = edgef(p2, dp1, (u32)(m1 >> (jA + 8)) & 1u);
                float eD = edgef(p3, dp1, (u32)(m1 >> (jA + 9)) & 1u);
                ahi[1] = packbf2(eA, eB);
                ahi[3] = packbf2(eC, eD);
            }

            // rowsum of the quantized weights via ones-B MMA
            mma16816(accrs, ahi, ONES2, ONES2);

            // B fragments via ldmatrix
            u32 bh[16], bl[16];
            const int bchunk = 2 * q + (sub & 1);
#pragma unroll
            for (int g = 0; g < 4; g++) {
                u32 off = swzf((u32)((g * 16 + brow) * 128 + bchunk * 16));
                ldsm4(bh + g * 4, su_hi + off);
                ldsm4(bl + g * 4, su_lo + off);
            }
#pragma unroll
            for (int g = 0; g < 4; g++) {
#pragma unroll
                for (int m = 0; m < 2; m++) {
                    int ng = g * 2 + m;
                    u32 h0 = bh[g * 4 + 2 * m], h1 = bh[g * 4 + 2 * m + 1];
                    u32 l0 = bl[g * 4 + 2 * m], l1 = bl[g * 4 + 2 * m + 1];
                    mma16816(acc[ng], ahi, h0, h1);
                    mma16816(acc[ng], ahi, l0, l1);
                }
            }
        }
        __syncthreads();
    }

    float rinv0 = 1.0f / accrs[0];
    float rinv1 = 1.0f / accrs[2];

    float* orow0 = xout + (size_t)(b * NT + i0 + r0) * fs + h * 64;
    float* orow1 = xout + (size_t)(b * NT + i0 + r1) * fs + h * 64;
#pragma unroll
    for (int ng = 0; ng < 8; ng++) {
        int col = ng * 8 + 2 * (l & 3);
        float2 bb = *(const float2*)(bias + h * 64 + col);
        float2 o0, o1;
        o0.x = fmaxf(acc[ng][0] * rinv0 + bb.x, 0.f);
        o0.y = fmaxf(acc[ng][1] * rinv0 + bb.y, 0.f);
        o1.x = fmaxf(acc[ng][2] * rinv1 + bb.x, 0.f);
        o1.y = fmaxf(acc[ng][3] * rinv1 + bb.y, 0.f);
        *(float2*)(orow0 + col) = o0;
        *(float2*)(orow1 + col) = o1;
    }
}

// ---------------- readout --------------------------------------------------
__global__ void gsum_kernel(const float* __restrict__ x, float* __restrict__ g) {
    int b = blockIdx.x;
    int tid = threadIdx.x;
    int c = tid & 63, nq = tid >> 6;
    float acc = 0.f;
    for (int n = nq; n < NT; n += 4) acc += x[((size_t)b * NT + n) * 64 + c];
    __shared__ float sm[256];
    sm[tid] = acc;
    __syncthreads();
    if (tid < 64) g[b * 64 + tid] = sm[tid] + sm[64 + tid] + sm[128 + tid] + sm[192 + tid];
}

__global__ void z2_kernel(const float* __restrict__ g, const float* __restrict__ wg,
                          const float* __restrict__ bg, const float* __restrict__ wv,
                          float* __restrict__ z2) {
    int b = blockIdx.x;
    int c = threadIdx.x;
    float acc = bg[c];
    for (int k = 0; k < 64; k++) acc += g[b * 64 + k] * wg[c * 64 + k];
    float y = fmaxf(acc, 0.f) * wv[64 + c];
    __shared__ float sm[64];
    sm[c] = y;
    __syncthreads();
    if (c == 0) {
        float t = 0.f;
        for (int k = 0; k < 64; k++) t += sm[k];
        z2[b] = t;
    }
}

__global__ __launch_bounds__(256) void final_kernel(
    const float* __restrict__ x,
    const float* __restrict__ wn, const float* __restrict__ bn,
    const float* __restrict__ wv, const float* __restrict__ bv,
    const float* __restrict__ z2, float* __restrict__ out)
{
    __shared__ float wns[64][65];
    __shared__ float bns[64], wvs[64];
    int tid = threadIdx.x;
#pragma unroll
    for (int l = 0; l < 16; l++) {
        int f = tid + l * 256;
        wns[f >> 6][f & 63] = wn[f];
    }
    if (tid < 64) { bns[tid] = bn[tid]; wvs[tid] = wv[tid]; }
    __syncthreads();

    int row = blockIdx.x * 64 + (tid >> 2);
    int q = tid & 3;
    float xr[64];
#pragma unroll
    for (int k = 0; k < 64; k++) xr[k] = x[(size_t)row * 64 + k];
    float y = 0.f;
    for (int c16 = 0; c16 < 16; c16++) {
        int c = q * 16 + c16;
        float acc = bns[c];
#pragma unroll
        for (int k = 0; k < 64; k++) acc += xr[k] * wns[c][k];
        y += fmaxf(acc, 0.f) * wvs[c];
    }
    y += __shfl_xor_sync(0xffffffffu, y, 1);
    y += __shfl_xor_sync(0xffffffffu, y, 2);
    if (q == 0) out[row] = y + z2[row >> 10] + bv[0];
}

// ---------------- launch ----------------------------------------------------
extern "C" void kernel_launch(void* const* d_in, const int* in_sizes, int n_in,
                              void* d_out, int out_size)
{
    const float* xin = (const float*)d_in[0];
    const int*   adj = (const int*)d_in[1];
    const float* w1  = (const float*)d_in[2];
    const float* as1 = (const float*)d_in[3];
    const float* ad1 = (const float*)d_in[4];
    const float* b1  = (const float*)d_in[5];
    const float* w2  = (const float*)d_in[6];
    const float* as2 = (const float*)d_in[7];
    const float* ad2 = (const float*)d_in[8];
    const float* b2  = (const float*)d_in[9];
    const float* w3  = (const float*)d_in[10];
    const float* as3 = (const float*)d_in[11];
    const float* ad3 = (const float*)d_in[12];
    const float* b3  = (const float*)d_in[13];
    const float* wn  = (const float*)d_in[14];
    const float* bn  = (const float*)d_in[15];
    const float* wg  = (const float*)d_in[16];
    const float* bg  = (const float*)d_in[17];
    const float* wv  = (const float*)d_in[18];
    const float* bv  = (const float*)d_in[19];
    float* out = (float*)d_out;

    float *bufA, *bufB, *gsm, *z2p;
    float4 *spk, *dpk;
    __nv_bfloat16 *hhi, *hlo;
    u32* bits;
    cudaGetSymbolAddress((void**)&bufA, g_bufA);
    cudaGetSymbolAddress((void**)&bufB, g_bufB);
    cudaGetSymbolAddress((void**)&spk,  g_spk);
    cudaGetSymbolAddress((void**)&dpk,  g_dpk);
    cudaGetSymbolAddress((void**)&hhi,  g_hThi);
    cudaGetSymbolAddress((void**)&hlo,  g_hTlo);
    cudaGetSymbolAddress((void**)&bits, g_bits);
    cudaGetSymbolAddress((void**)&gsm,  g_gsum);
    cudaGetSymbolAddress((void**)&z2p,  g_z2);

    cudaFuncSetAttribute(agg_mma_kernel, cudaFuncAttributeMaxDynamicSharedMemorySize, AGG_SMEM);

    const int M = BATCH * NT;
    const ull* bits64 = (const ull*)bits;

    pack_adj_kernel<<<M, 32>>>(adj, bits);

    // layer 1: 64 -> 4x64 (gemm + scores + split-transpose fused)
    gemm_fused<<<dim3(M / 128, 4), 256>>>(xin, w1, as1, ad1,
                                          spk, dpk, hhi, hlo, 64);
    agg_mma_kernel<<<dim3(NT / 128, 4, BATCH), 256, AGG_SMEM>>>(
        hhi, hlo, spk, dpk, bits64, b1, bufB, 4);

    // layer 2: 4x64 -> 4x64
    gemm_fused<<<dim3(M / 128, 4), 256>>>(bufB, w2, as2, ad2,
                                          spk, dpk, hhi, hlo, 256);
    agg_mma_kernel<<<dim3(NT / 128, 4, BATCH), 256, AGG_SMEM>>>(
        hhi, hlo, spk, dpk, bits64, b2, bufA, 4);

    // layer 3: 4x64 -> 64 (H=1)
    gemm_fused<<<dim3(M / 128, 1), 256>>>(bufA, w3, as3, ad3,
                                          spk, dpk, hhi, hlo, 256);
    agg_mma_kernel<<<dim3(NT / 128, 1, BATCH), 256, AGG_SMEM>>>(
        hhi, hlo, spk, dpk, bits64, b3, bufB, 1);

    // readout
    gsum_kernel<<<BATCH, 256>>>(bufB, gsm);
    z2_kernel<<<BATCH, 64>>>(gsm, wg, bg, wv, z2p);
    final_kernel<<<M / 64, 256>>>(bufB, wn, bn, wv, bv, z2p, out);
}

// round 12
// speedup vs baseline: 1.2737x; 1.2737x over previous
#include <cuda_runtime.h>
#include <cuda_fp16.h>
#include <cstdint>

#define BATCH 8
#define NT    1024
typedef unsigned long long ull;
typedef unsigned int u32;

// ---------------- scratch (__device__ globals; no allocation allowed) ------
__device__ __align__(16) float g_bufA[BATCH * NT * 256];
__device__ __align__(16) float g_bufB[BATCH * NT * 256];
// packed source scores (s, Es, Es2, 0) and dest scores (d, Ed, Ed2, 0), [h][b][node]
__device__ __align__(16) float4 g_spk[4 * BATCH * NT];
__device__ __align__(16) float4 g_dpk[4 * BATCH * NT];
// pre-transposed fp16 features [h][b][c=64][node=1024]
__device__ __align__(16) __half g_hT[4 * BATCH * 64 * NT];
__device__ __align__(16) u32   g_bits[BATCH * NT * (NT / 32)];
__device__ __align__(16) float g_gsum[BATCH * 64];
__device__ __align__(16) float g_z2[BATCH];

// ---------------- helpers --------------------------------------------------
__device__ __forceinline__ uint32_t smem_u32(const void* p) {
    uint32_t a;
    asm("{ .reg .u64 t; cvta.to.shared.u64 t, %1; cvt.u32.u64 %0, t; }" : "=r"(a) : "l"(p));
    return a;
}

__device__ __forceinline__ void ldsm4(u32* r, u32 addr) {
    asm volatile("ldmatrix.sync.aligned.m8n8.x4.shared.b16 {%0,%1,%2,%3}, [%4];"
                 : "=r"(r[0]), "=r"(r[1]), "=r"(r[2]), "=r"(r[3]) : "r"(addr));
}

__device__ __forceinline__ void mmaf16(float* c, const u32* a, u32 b0, u32 b1) {
    asm volatile(
        "mma.sync.aligned.m16n8k16.row.col.f32.f16.f16.f32 "
        "{%0,%1,%2,%3}, {%4,%5,%6,%7}, {%8,%9}, {%0,%1,%2,%3};"
        : "+f"(c[0]), "+f"(c[1]), "+f"(c[2]), "+f"(c[3])
        : "r"(a[0]), "r"(a[1]), "r"(a[2]), "r"(a[3]), "r"(b0), "r"(b1));
}

// e_ij = adjbit * ( s_j + d_i > 0 ? Es_j*Ed_i : Es2_j*Ed2_i )
__device__ __forceinline__ float edgef(float4 p, float4 dp, u32 bit) {
    float e = (p.x + dp.x > 0.f) ? p.y * dp.y : p.z * dp.z;
    return bit ? e : 0.f;
}

// pack two fp32 into f16x2 (lower = ex, upper = ey) in one cvt
__device__ __forceinline__ u32 packh2(float ex, float ey) {
    u32 r;
    asm("cvt.rn.f16x2.f32 %0, %1, %2;" : "=r"(r) : "f"(ey), "f"(ex));
    return r;
}

// fp16 hi/lo split of a pair, packed
__device__ __forceinline__ void split2h(float x0, float x1, u32& hi, u32& lo) {
    hi = packh2(x0, x1);
    __half2 hv = *(__half2*)&hi;
    float2 bk = __half22float2(hv);
    lo = packh2(x0 - bk.x, x1 - bk.y);
}

__device__ __forceinline__ u32 swzf(u32 off) { return off ^ ((off >> 3) & 0x70); }

#define ONESH 0x3C003C00u   // two fp16 1.0

// ---------------- adj bit packing (with self loops) ------------------------
__global__ void pack_adj_kernel(const int* __restrict__ adj, u32* __restrict__ bits) {
    int row = blockIdx.x;                 // b*NT + i
    int lane = threadIdx.x;               // 32 threads
    int i = row & (NT - 1);
    const int* arow = adj + (size_t)row * NT;
    for (int w = 0; w < 32; w++) {
        int j = w * 32 + lane;
        int v = arow[j];
        unsigned m = __ballot_sync(0xffffffffu, (v > 0) || (j == i));
        if (lane == 0) bits[row * 32 + w] = m;
    }
}

// ---------------- fused HMMA feature GEMM + scores + fp16 transpose --------
// fp16 hi/lo split on both operands, 3 MMA passes (error ~2^-22).
// Epilogue: scores (+exp factors) and single-fp16 transposed feature write.
#define TPAD 136
__global__ __launch_bounds__(256) void gemm_fused(
    const float* __restrict__ X, const float* __restrict__ W,
    const float* __restrict__ a_src, const float* __restrict__ a_dst,
    float4* __restrict__ spk, float4* __restrict__ dpk,
    __half* __restrict__ hT, int K)
{
    __shared__ __align__(128) char smbuf[49152];
    __half* sXh = (__half*)(smbuf);
    __half* sXl = (__half*)(smbuf + 16384);
    __half* sWh = (__half*)(smbuf + 32768);
    __half* sWl = (__half*)(smbuf + 40960);

    const int tid = threadIdx.x;
    const int w = tid >> 5, l = tid & 31;
    const int h = blockIdx.y;
    const int m0 = blockIdx.x * 128, n0 = h * 64;

    const u32 uXh = smem_u32(sXh), uXl = smem_u32(sXl);
    const u32 uWh = smem_u32(sWh), uWl = smem_u32(sWl);

    float acc[8][4];
#pragma unroll
    for (int ng = 0; ng < 8; ng++)
#pragma unroll
        for (int r = 0; r < 4; r++) acc[ng][r] = 0.f;

    const int arow = w * 16 + (l & 7) + ((l >> 3) & 1) * 8;
    const int akh  = (l >> 4);
    const int sub = l >> 3;
    const int brow = (l & 7) + ((sub >> 1) << 3);

    for (int k0 = 0; k0 < K; k0 += 64) {
        __syncthreads();
#pragma unroll
        for (int i = 0; i < 4; i++) {
            int c = tid + i * 256;
            int row = c >> 3, kg = c & 7;
            const float* p = X + (size_t)(m0 + row) * K + k0 + kg * 8;
            float4 v0 = *(const float4*)p;
            float4 v1 = *(const float4*)(p + 4);
            u32 h0, h1, h2, h3, l0, l1, l2, l3;
            split2h(v0.x, v0.y, h0, l0); split2h(v0.z, v0.w, h1, l1);
            split2h(v1.x, v1.y, h2, l2); split2h(v1.z, v1.w, h3, l3);
            u32 off = swzf((u32)(row * 128 + kg * 16));
            *(uint4*)((char*)sXh + off) = make_uint4(h0, h1, h2, h3);
            *(uint4*)((char*)sXl + off) = make_uint4(l0, l1, l2, l3);
        }
#pragma unroll
        for (int i = 0; i < 2; i++) {
            int c = tid + i * 256;
            int row = c >> 3, kg = c & 7;
            const float* p = W + (size_t)(n0 + row) * K + k0 + kg * 8;
            float4 v0 = *(const float4*)p;
            float4 v1 = *(const float4*)(p + 4);
            u32 h0, h1, h2, h3, l0, l1, l2, l3;
            split2h(v0.x, v0.y, h0, l0); split2h(v0.z, v0.w, h1, l1);
            split2h(v1.x, v1.y, h2, l2); split2h(v1.z, v1.w, h3, l3);
            u32 off = swzf((u32)(row * 128 + kg * 16));
            *(uint4*)((char*)sWh + off) = make_uint4(h0, h1, h2, h3);
            *(uint4*)((char*)sWl + off) = make_uint4(l0, l1, l2, l3);
        }
        __syncthreads();

#pragma unroll
        for (int q = 0; q < 4; q++) {
            u32 ah[4], al[4];
            u32 aoff = swzf((u32)(arow * 128 + q * 32 + akh * 16));
            ldsm4(ah, uXh + aoff);
            ldsm4(al, uXl + aoff);
            const int bchunk = 2 * q + (sub & 1);
            u32 bh[16], bl[16];
#pragma unroll
            for (int g = 0; g < 4; g++) {
                u32 off = swzf((u32)((g * 16 + brow) * 128 + bchunk * 16));
                ldsm4(bh + g * 4, uWh + off);
                ldsm4(bl + g * 4, uWl + off);
            }
#pragma unroll
            for (int g = 0; g < 4; g++) {
#pragma unroll
                for (int m = 0; m < 2; m++) {
                    int ng = g * 2 + m;
                    u32 b0 = bh[g * 4 + 2 * m], b1 = bh[g * 4 + 2 * m + 1];
                    u32 c0 = bl[g * 4 + 2 * m], c1 = bl[g * 4 + 2 * m + 1];
                    mmaf16(acc[ng], ah, b0, b1);
                    mmaf16(acc[ng], ah, c0, c1);
                    mmaf16(acc[ng], al, b0, b1);
                }
            }
        }
    }

    const int r0 = w * 16 + (l >> 2);
    const int r1 = r0 + 8;

    // ---- epilogue 1: attention scores (4-lane reduce) ----
    {
        float s0 = 0.f, d0 = 0.f, s1 = 0.f, d1 = 0.f;
#pragma unroll
        for (int ng = 0; ng < 8; ng++) {
            int col = ng * 8 + 2 * (l & 3);
            float2 av = *(const float2*)(a_src + n0 + col);
            float2 dv = *(const float2*)(a_dst + n0 + col);
            s0 += acc[ng][0] * av.x + acc[ng][1] * av.y;
            d0 += acc[ng][0] * dv.x + acc[ng][1] * dv.y;
            s1 += acc[ng][2] * av.x + acc[ng][3] * av.y;
            d1 += acc[ng][2] * dv.x + acc[ng][3] * dv.y;
        }
        s0 += __shfl_xor_sync(0xffffffffu, s0, 1);
        s0 += __shfl_xor_sync(0xffffffffu, s0, 2);
        d0 += __shfl_xor_sync(0xffffffffu, d0, 1);
        d0 += __shfl_xor_sync(0xffffffffu, d0, 2);
        s1 += __shfl_xor_sync(0xffffffffu, s1, 1);
        s1 += __shfl_xor_sync(0xffffffffu, s1, 2);
        d1 += __shfl_xor_sync(0xffffffffu, d1, 1);
        d1 += __shfl_xor_sync(0xffffffffu, d1, 2);
        if ((l & 3) == 0) {
            int idx0 = h * (BATCH * NT) + m0 + r0;
            int idx1 = h * (BATCH * NT) + m0 + r1;
            spk[idx0] = make_float4(s0, __expf(s0), __expf(0.2f * s0), 0.f);
            dpk[idx0] = make_float4(d0, __expf(d0), __expf(0.2f * d0), 0.f);
            spk[idx1] = make_float4(s1, __expf(s1), __expf(0.2f * s1), 0.f);
            dpk[idx1] = make_float4(d1, __expf(d1), __expf(0.2f * d1), 0.f);
        }
    }

    // ---- epilogue 2: single fp16 quantize + transpose via smem bounce ----
    __syncthreads();
    unsigned short* Th = (unsigned short*)(smbuf);            // [64][TPAD]
#pragma unroll
    for (int ng = 0; ng < 8; ng++) {
        int col = ng * 8 + 2 * (l & 3);
#pragma unroll
        for (int v = 0; v < 4; v++) {
            int cc = col + (v & 1);
            int node = (v < 2) ? r0 : r1;
            u32 p = packh2(acc[ng][v], 0.f);
            Th[cc * TPAD + node] = (unsigned short)(p & 0xffffu);
        }
    }
    __syncthreads();

    const int b = m0 >> 10;
    const int node0 = m0 & (NT - 1);
    const size_t gbase = ((size_t)((h * BATCH + b) * 64)) * NT + node0;
    {
        int c = tid >> 2;
#pragma unroll
        for (int i = 0; i < 4; i++) {
            int nch = (tid & 3) + 4 * i;
            uint4 vh = *(const uint4*)(Th + c * TPAD + nch * 8);
            *(uint4*)(hT + gbase + (size_t)c * NT + nch * 8) = vh;
        }
    }
}

// ---------------- HMMA aggregation (fp16 single-pass) ----------------------
// grid (NT/128, H, B), 256 threads = 8 warps; warp w owns rows w*16..w*16+15.
// D[i,c] = sum_j E[i,j]*h[j,c]; E and h fp16, fp32 accum.
// Rowsum = MMA of the same quantized A fragment against all-ones B (exact
// cancellation of correlated E quantization in the normalization).
__global__ __launch_bounds__(256, 2) void agg_mma_kernel(
    const __half* __restrict__ hTA,
    const float4* __restrict__ spkA, const float4* __restrict__ dpkA,
    const ull* __restrict__ bits64,
    const float* __restrict__ bias, float* __restrict__ xout, int H)
{
    __shared__ __align__(16) __half sh_h[2][64 * 64];
    __shared__ __align__(16) float4 sh_sp[2][64];

    const int tid = threadIdx.x;
    const int w = tid >> 5, l = tid & 31;
    const int b = blockIdx.z, h = blockIdx.y;
    const int i0 = blockIdx.x * 128;
    const int hb = h * BATCH + b;
    const int fs = H * 64;

    const int r0 = w * 16 + (l >> 2);
    const int r1 = r0 + 8;
    const float4 dp0 = dpkA[hb * NT + i0 + r0];
    const float4 dp1 = dpkA[hb * NT + i0 + r1];
    const ull* mrow0 = bits64 + (size_t)(b * NT + i0 + r0) * 16;
    const ull* mrow1 = bits64 + (size_t)(b * NT + i0 + r1) * 16;

    const float4* spkp = spkA + hb * NT;
    const __half* hhp = hTA + (size_t)hb * 64 * NT;

    const int c0 = tid >> 3, jc = tid & 7;
    const u32 st0 = swzf((u32)(c0 * 128 + jc * 16));
    const u32 st1 = swzf((u32)((c0 + 32) * 128 + jc * 16));

    float acc[8][4];
#pragma unroll
    for (int ng = 0; ng < 8; ng++)
#pragma unroll
        for (int r = 0; r < 4; r++) acc[ng][r] = 0.f;
    float accrs[4] = {0.f, 0.f, 0.f, 0.f};

    uint4 pvh0, pvh1;
    float4 psc = make_float4(0.f, 0.f, 0.f, 0.f);

    auto ldg_tile = [&](int t) {
        int j0 = t * 64;
        pvh0 = *(const uint4*)(hhp + (size_t)c0 * NT + j0 + jc * 8);
        pvh1 = *(const uint4*)(hhp + (size_t)(c0 + 32) * NT + j0 + jc * 8);
        if (tid < 64) psc = spkp[j0 + tid];
    };

    ldg_tile(0);

    const u32 su[2] = { smem_u32(sh_h[0]), smem_u32(sh_h[1]) };

    const int sub = l >> 3;
    const int brow = (l & 7) + ((sub >> 1) << 3);

    for (int t = 0; t < 16; t++) {
        int buf = t & 1;
        *(uint4*)((char*)sh_h[buf] + st0) = pvh0;
        *(uint4*)((char*)sh_h[buf] + st1) = pvh1;
        if (tid < 64) sh_sp[buf][tid] = psc;
        __syncthreads();
        if (t < 15) ldg_tile(t + 1);

        const float4* sp = sh_sp[buf];
        const ull m0 = mrow0[t];
        const ull m1 = mrow1[t];

#pragma unroll
        for (int q = 0; q < 4; q++) {
            const int jA = q * 16 + 2 * (l & 3);
            float4 p0 = sp[jA], p1 = sp[jA + 1], p2 = sp[jA + 8], p3 = sp[jA + 9];

            u32 ahi[4];
            // row r0
            {
                float eA = edgef(p0, dp0, (u32)(m0 >> jA) & 1u);
                float eB = edgef(p1, dp0, (u32)(m0 >> (jA + 1)) & 1u);
                float eC = edgef(p2, dp0, (u32)(m0 >> (jA + 8)) & 1u);
                float eD = edgef(p3, dp0, (u32)(m0 >> (jA + 9)) & 1u);
                ahi[0] = packh2(eA, eB);
                ahi[2] = packh2(eC, eD);
            }
            // row r1
            {
                float eA = edgef(p0, dp1, (u32)(m1 >> jA) & 1u);
                float eB = edgef(p1, dp1, (u32)(m1 >> (jA + 1)) & 1u);
                float eC = edgef(p2, dp1, (u32)(m1 >> (jA + 8)) & 1u);
                float eD = edgef(p3, dp1, (u32)(m1 >> (jA + 9)) & 1u);
                ahi[1] = packh2(eA, eB);
                ahi[3] = packh2(eC, eD);
            }

            // rowsum of the quantized weights via ones-B MMA
            mmaf16(accrs, ahi, ONESH, ONESH);

            // B fragments via ldmatrix
            u32 bh[16];
            const int bchunk = 2 * q + (sub & 1);
#pragma unroll
            for (int g = 0; g < 4; g++) {
                u32 off = swzf((u32)((g * 16 + brow) * 128 + bchunk * 16));
                ldsm4(bh + g * 4, su[buf] + off);
            }
#pragma unroll
            for (int g = 0; g < 4; g++) {
#pragma unroll
                for (int m = 0; m < 2; m++) {
                    int ng = g * 2 + m;
                    mmaf16(acc[ng], ahi, bh[g * 4 + 2 * m], bh[g * 4 + 2 * m + 1]);
                }
            }
        }
        __syncthreads();
    }

    float rinv0 = 1.0f / accrs[0];
    float rinv1 = 1.0f / accrs[2];

    float* orow0 = xout + (size_t)(b * NT + i0 + r0) * fs + h * 64;
    float* orow1 = xout + (size_t)(b * NT + i0 + r1) * fs + h * 64;
#pragma unroll
    for (int ng = 0; ng < 8; ng++) {
        int col = ng * 8 + 2 * (l & 3);
        float2 bb = *(const float2*)(bias + h * 64 + col);
        float2 o0, o1;
        o0.x = fmaxf(acc[ng][0] * rinv0 + bb.x, 0.f);
        o0.y = fmaxf(acc[ng][1] * rinv0 + bb.y, 0.f);
        o1.x = fmaxf(acc[ng][2] * rinv1 + bb.x, 0.f);
        o1.y = fmaxf(acc[ng][3] * rinv1 + bb.y, 0.f);
        *(float2*)(orow0 + col) = o0;
        *(float2*)(orow1 + col) = o1;
    }
}

// ---------------- readout --------------------------------------------------
__global__ void gsum_kernel(const float* __restrict__ x, float* __restrict__ g) {
    int b = blockIdx.x;
    int tid = threadIdx.x;
    int c = tid & 63, nq = tid >> 6;
    float acc = 0.f;
    for (int n = nq; n < NT; n += 4) acc += x[((size_t)b * NT + n) * 64 + c];
    __shared__ float sm[256];
    sm[tid] = acc;
    __syncthreads();
    if (tid < 64) g[b * 64 + tid] = sm[tid] + sm[64 + tid] + sm[128 + tid] + sm[192 + tid];
}

__global__ void z2_kernel(const float* __restrict__ g, const float* __restrict__ wg,
                          const float* __restrict__ bg, const float* __restrict__ wv,
                          float* __restrict__ z2) {
    int b = blockIdx.x;
    int c = threadIdx.x;
    float acc = bg[c];
    for (int k = 0; k < 64; k++) acc += g[b * 64 + k] * wg[c * 64 + k];
    float y = fmaxf(acc, 0.f) * wv[64 + c];
    __shared__ float sm[64];
    sm[c] = y;
    __syncthreads();
    if (c == 0) {
        float t = 0.f;
        for (int k = 0; k < 64; k++) t += sm[k];
        z2[b] = t;
    }
}

__global__ __launch_bounds__(256) void final_kernel(
    const float* __restrict__ x,
    const float* __restrict__ wn, const float* __restrict__ bn,
    const float* __restrict__ wv, const float* __restrict__ bv,
    const float* __restrict__ z2, float* __restrict__ out)
{
    __shared__ float wns[64][65];
    __shared__ float bns[64], wvs[64];
    int tid = threadIdx.x;
#pragma unroll
    for (int l = 0; l < 16; l++) {
        int f = tid + l * 256;
        wns[f >> 6][f & 63] = wn[f];
    }
    if (tid < 64) { bns[tid] = bn[tid]; wvs[tid] = wv[tid]; }
    __syncthreads();

    int row = blockIdx.x * 64 + (tid >> 2);
    int q = tid & 3;
    float xr[64];
#pragma unroll
    for (int k = 0; k < 64; k++) xr[k] = x[(size_t)row * 64 + k];
    float y = 0.f;
    for (int c16 = 0; c16 < 16; c16++) {
        int c = q * 16 + c16;
        float acc = bns[c];
#pragma unroll
        for (int k = 0; k < 64; k++) acc += xr[k] * wns[c][k];
        y += fmaxf(acc, 0.f) * wvs[c];
    }
    y += __shfl_xor_sync(0xffffffffu, y, 1);
    y += __shfl_xor_sync(0xffffffffu, y, 2);
    if (q == 0) out[row] = y + z2[row >> 10] + bv[0];
}

// ---------------- launch ----------------------------------------------------
extern "C" void kernel_launch(void* const* d_in, const int* in_sizes, int n_in,
                              void* d_out, int out_size)
{
    const float* xin = (const float*)d_in[0];
    const int*   adj = (const int*)d_in[1];
    const float* w1  = (const float*)d_in[2];
    const float* as1 = (const float*)d_in[3];
    const float* ad1 = (const float*)d_in[4];
    const float* b1  = (const float*)d_in[5];
    const float* w2  = (const float*)d_in[6];
    const float* as2 = (const float*)d_in[7];
    const float* ad2 = (const float*)d_in[8];
    const float* b2  = (const float*)d_in[9];
    const float* w3  = (const float*)d_in[10];
    const float* as3 = (const float*)d_in[11];
    const float* ad3 = (const float*)d_in[12];
    const float* b3  = (const float*)d_in[13];
    const float* wn  = (const float*)d_in[14];
    const float* bn  = (const float*)d_in[15];
    const float* wg  = (const float*)d_in[16];
    const float* bg  = (const float*)d_in[17];
    const float* wv  = (const float*)d_in[18];
    const float* bv  = (const float*)d_in[19];
    float* out = (float*)d_out;

    float *bufA, *bufB, *gsm, *z2p;
    float4 *spk, *dpk;
    __half* hT;
    u32* bits;
    cudaGetSymbolAddress((void**)&bufA, g_bufA);
    cudaGetSymbolAddress((void**)&bufB, g_bufB);
    cudaGetSymbolAddress((void**)&spk,  g_spk);
    cudaGetSymbolAddress((void**)&dpk,  g_dpk);
    cudaGetSymbolAddress((void**)&hT,   g_hT);
    cudaGetSymbolAddress((void**)&bits, g_bits);
    cudaGetSymbolAddress((void**)&gsm,  g_gsum);
    cudaGetSymbolAddress((void**)&z2p,  g_z2);

    const int M = BATCH * NT;
    const ull* bits64 = (const ull*)bits;

    pack_adj_kernel<<<M, 32>>>(adj, bits);

    // layer 1: 64 -> 4x64 (gemm + scores + fp16 transpose fused)
    gemm_fused<<<dim3(M / 128, 4), 256>>>(xin, w1, as1, ad1, spk, dpk, hT, 64);
    agg_mma_kernel<<<dim3(NT / 128, 4, BATCH), 256>>>(
        hT, spk, dpk, bits64, b1, bufB, 4);

    // layer 2: 4x64 -> 4x64
    gemm_fused<<<dim3(M / 128, 4), 256>>>(bufB, w2, as2, ad2, spk, dpk, hT, 256);
    agg_mma_kernel<<<dim3(NT / 128, 4, BATCH), 256>>>(
        hT, spk, dpk, bits64, b2, bufA, 4);

    // layer 3: 4x64 -> 64 (H=1)
    gemm_fused<<<dim3(M / 128, 1), 256>>>(bufA, w3, as3, ad3, spk, dpk, hT, 256);
    agg_mma_kernel<<<dim3(NT / 128, 1, BATCH), 256>>>(
        hT, spk, dpk, bits64, b3, bufB, 1);

    // readout
    gsum_kernel<<<BATCH, 256>>>(bufB, gsm);
    z2_kernel<<<BATCH, 64>>>(gsm, wg, bg, wv, z2p);
    final_kernel<<<M / 64, 256>>>(bufB, wn, bn, wv, bv, z2p, out);
}

// round 13
// speedup vs baseline: 1.3921x; 1.0930x over previous
#include <cuda_runtime.h>
#include <cuda_fp16.h>
#include <cstdint>

#define BATCH 8
#define NT    1024
typedef unsigned long long ull;
typedef unsigned int u32;

// ---------------- scratch (__device__ globals; no allocation allowed) ------
__device__ __align__(16) float g_bufB[BATCH * NT * 64];      // layer3 f32 out
// inter-layer features pre-split to fp16 hi/lo planes [b][node][fs]
__device__ __align__(16) __half g_xhi[BATCH * NT * 256];
__device__ __align__(16) __half g_xlo[BATCH * NT * 256];
// fp16 weights (single plane)
__device__ __align__(16) __half g_w2h[256 * 256];
__device__ __align__(16) __half g_w3h[64 * 256];
// packed source scores (s, Es, Es2, 0) and dest scores (d, Ed, Ed2, 0), [h][b][node]
__device__ __align__(16) float4 g_spk[4 * BATCH * NT];
__device__ __align__(16) float4 g_dpk[4 * BATCH * NT];
// pre-transposed fp16 features [h][b][c=64][node=1024]
__device__ __align__(16) __half g_hT[4 * BATCH * 64 * NT];
__device__ __align__(16) u32   g_bits[BATCH * NT * (NT / 32)];
__device__ __align__(16) float g_gsum[BATCH * 64];
__device__ __align__(16) float g_z2[BATCH];

// ---------------- helpers --------------------------------------------------
__device__ __forceinline__ uint32_t smem_u32(const void* p) {
    uint32_t a;
    asm("{ .reg .u64 t; cvta.to.shared.u64 t, %1; cvt.u32.u64 %0, t; }" : "=r"(a) : "l"(p));
    return a;
}

__device__ __forceinline__ void ldsm4(u32* r, u32 addr) {
    asm volatile("ldmatrix.sync.aligned.m8n8.x4.shared.b16 {%0,%1,%2,%3}, [%4];"
                 : "=r"(r[0]), "=r"(r[1]), "=r"(r[2]), "=r"(r[3]) : "r"(addr));
}

__device__ __forceinline__ void mmaf16(float* c, const u32* a, u32 b0, u32 b1) {
    asm volatile(
        "mma.sync.aligned.m16n8k16.row.col.f32.f16.f16.f32 "
        "{%0,%1,%2,%3}, {%4,%5,%6,%7}, {%8,%9}, {%0,%1,%2,%3};"
        : "+f"(c[0]), "+f"(c[1]), "+f"(c[2]), "+f"(c[3])
        : "r"(a[0]), "r"(a[1]), "r"(a[2]), "r"(a[3]), "r"(b0), "r"(b1));
}

// e_ij = adjbit * ( s_j + d_i > 0 ? Es_j*Ed_i : Es2_j*Ed2_i )
__device__ __forceinline__ float edgef(float4 p, float4 dp, u32 bit) {
    float e = (p.x + dp.x > 0.f) ? p.y * dp.y : p.z * dp.z;
    return bit ? e : 0.f;
}

// pack two fp32 into f16x2 (lower = ex, upper = ey) in one cvt
__device__ __forceinline__ u32 packh2(float ex, float ey) {
    u32 r;
    asm("cvt.rn.f16x2.f32 %0, %1, %2;" : "=r"(r) : "f"(ey), "f"(ex));
    return r;
}

// fp16 hi/lo split of a pair, packed
__device__ __forceinline__ void split2h(float x0, float x1, u32& hi, u32& lo) {
    hi = packh2(x0, x1);
    __half2 hv = *(__half2*)&hi;
    float2 bk = __half22float2(hv);
    lo = packh2(x0 - bk.x, x1 - bk.y);
}

__device__ __forceinline__ u32 swzf(u32 off) { return off ^ ((off >> 3) & 0x70); }

__device__ __forceinline__ void cpasync16(u32 dst, const void* src) {
    asm volatile("cp.async.cg.shared.global [%0], [%1], 16;" :: "r"(dst), "l"(src) : "memory");
}
#define CP_COMMIT() asm volatile("cp.async.commit_group;" ::: "memory")
#define CP_WAIT0()  asm volatile("cp.async.wait_group 0;" ::: "memory")

#define ONESH 0x3C003C00u   // two fp16 1.0

// ---------------- adj bit packing (with self loops) ------------------------
__global__ void pack_adj_kernel(const int* __restrict__ adj, u32* __restrict__ bits) {
    int row = blockIdx.x;
    int lane = threadIdx.x;
    int i = row & (NT - 1);
    const int* arow = adj + (size_t)row * NT;
    for (int w = 0; w < 32; w++) {
        int j = w * 32 + lane;
        int v = arow[j];
        unsigned m = __ballot_sync(0xffffffffu, (v > 0) || (j == i));
        if (lane == 0) bits[row * 32 + w] = m;
    }
}

// ---------------- f32 -> fp16 weight convert -------------------------------
__global__ void convh_kernel(const float* __restrict__ src, __half* __restrict__ dst, int n4) {
    int i = blockIdx.x * 256 + threadIdx.x;
    if (i >= n4) return;
    float4 v = *(const float4*)(src + i * 4);
    uint2 o;
    o.x = packh2(v.x, v.y);
    o.y = packh2(v.z, v.w);
    *(uint2*)(dst + i * 4) = o;
}

// ---------------- layer-1 fused GEMM (f32 inputs, 3-pass fp16 split) -------
#define TPAD 136
__global__ __launch_bounds__(256) void gemm_fused(
    const float* __restrict__ X, const float* __restrict__ W,
    const float* __restrict__ a_src, const float* __restrict__ a_dst,
    float4* __restrict__ spk, float4* __restrict__ dpk,
    __half* __restrict__ hT, int K)
{
    __shared__ __align__(128) char smbuf[49152];
    __half* sXh = (__half*)(smbuf);
    __half* sXl = (__half*)(smbuf + 16384);
    __half* sWh = (__half*)(smbuf + 32768);
    __half* sWl = (__half*)(smbuf + 40960);

    const int tid = threadIdx.x;
    const int w = tid >> 5, l = tid & 31;
    const int h = blockIdx.y;
    const int m0 = blockIdx.x * 128, n0 = h * 64;

    const u32 uXh = smem_u32(sXh), uXl = smem_u32(sXl);
    const u32 uWh = smem_u32(sWh), uWl = smem_u32(sWl);

    float acc[8][4];
#pragma unroll
    for (int ng = 0; ng < 8; ng++)
#pragma unroll
        for (int r = 0; r < 4; r++) acc[ng][r] = 0.f;

    const int arow = w * 16 + (l & 7) + ((l >> 3) & 1) * 8;
    const int akh  = (l >> 4);
    const int sub = l >> 3;
    const int brow = (l & 7) + ((sub >> 1) << 3);

    for (int k0 = 0; k0 < K; k0 += 64) {
        __syncthreads();
#pragma unroll
        for (int i = 0; i < 4; i++) {
            int c = tid + i * 256;
            int row = c >> 3, kg = c & 7;
            const float* p = X + (size_t)(m0 + row) * K + k0 + kg * 8;
            float4 v0 = *(const float4*)p;
            float4 v1 = *(const float4*)(p + 4);
            u32 h0, h1, h2, h3, l0, l1, l2, l3;
            split2h(v0.x, v0.y, h0, l0); split2h(v0.z, v0.w, h1, l1);
            split2h(v1.x, v1.y, h2, l2); split2h(v1.z, v1.w, h3, l3);
            u32 off = swzf((u32)(row * 128 + kg * 16));
            *(uint4*)((char*)sXh + off) = make_uint4(h0, h1, h2, h3);
            *(uint4*)((char*)sXl + off) = make_uint4(l0, l1, l2, l3);
        }
#pragma unroll
        for (int i = 0; i < 2; i++) {
            int c = tid + i * 256;
            int row = c >> 3, kg = c & 7;
            const float* p = W + (size_t)(n0 + row) * K + k0 + kg * 8;
            float4 v0 = *(const float4*)p;
            float4 v1 = *(const float4*)(p + 4);
            u32 h0, h1, h2, h3, l0, l1, l2, l3;
            split2h(v0.x, v0.y, h0, l0); split2h(v0.z, v0.w, h1, l1);
            split2h(v1.x, v1.y, h2, l2); split2h(v1.z, v1.w, h3, l3);
            u32 off = swzf((u32)(row * 128 + kg * 16));
            *(uint4*)((char*)sWh + off) = make_uint4(h0, h1, h2, h3);
            *(uint4*)((char*)sWl + off) = make_uint4(l0, l1, l2, l3);
        }
        __syncthreads();

#pragma unroll
        for (int q = 0; q < 4; q++) {
            u32 ah[4], al[4];
            u32 aoff = swzf((u32)(arow * 128 + q * 32 + akh * 16));
            ldsm4(ah, uXh + aoff);
            ldsm4(al, uXl + aoff);
            const int bchunk = 2 * q + (sub & 1);
            u32 bh[16], bl[16];
#pragma unroll
            for (int g = 0; g < 4; g++) {
                u32 off = swzf((u32)((g * 16 + brow) * 128 + bchunk * 16));
                ldsm4(bh + g * 4, uWh + off);
                ldsm4(bl + g * 4, uWl + off);
            }
#pragma unroll
            for (int g = 0; g < 4; g++) {
#pragma unroll
                for (int m = 0; m < 2; m++) {
                    int ng = g * 2 + m;
                    u32 b0 = bh[g * 4 + 2 * m], b1 = bh[g * 4 + 2 * m + 1];
                    u32 c0 = bl[g * 4 + 2 * m], c1 = bl[g * 4 + 2 * m + 1];
                    mmaf16(acc[ng], ah, b0, b1);
                    mmaf16(acc[ng], ah, c0, c1);
                    mmaf16(acc[ng], al, b0, b1);
                }
            }
        }
    }

    const int r0 = w * 16 + (l >> 2);
    const int r1 = r0 + 8;

    // ---- epilogue 1: attention scores ----
    {
        float s0 = 0.f, d0 = 0.f, s1 = 0.f, d1 = 0.f;
#pragma unroll
        for (int ng = 0; ng < 8; ng++) {
            int col = ng * 8 + 2 * (l & 3);
            float2 av = *(const float2*)(a_src + n0 + col);
            float2 dv = *(const float2*)(a_dst + n0 + col);
            s0 += acc[ng][0] * av.x + acc[ng][1] * av.y;
            d0 += acc[ng][0] * dv.x + acc[ng][1] * dv.y;
            s1 += acc[ng][2] * av.x + acc[ng][3] * av.y;
            d1 += acc[ng][2] * dv.x + acc[ng][3] * dv.y;
        }
        s0 += __shfl_xor_sync(0xffffffffu, s0, 1);
        s0 += __shfl_xor_sync(0xffffffffu, s0, 2);
        d0 += __shfl_xor_sync(0xffffffffu, d0, 1);
        d0 += __shfl_xor_sync(0xffffffffu, d0, 2);
        s1 += __shfl_xor_sync(0xffffffffu, s1, 1);
        s1 += __shfl_xor_sync(0xffffffffu, s1, 2);
        d1 += __shfl_xor_sync(0xffffffffu, d1, 1);
        d1 += __shfl_xor_sync(0xffffffffu, d1, 2);
        if ((l & 3) == 0) {
            int idx0 = h * (BATCH * NT) + m0 + r0;
            int idx1 = h * (BATCH * NT) + m0 + r1;
            spk[idx0] = make_float4(s0, __expf(s0), __expf(0.2f * s0), 0.f);
            dpk[idx0] = make_float4(d0, __expf(d0), __expf(0.2f * d0), 0.f);
            spk[idx1] = make_float4(s1, __expf(s1), __expf(0.2f * s1), 0.f);
            dpk[idx1] = make_float4(d1, __expf(d1), __expf(0.2f * d1), 0.f);
        }
    }

    // ---- epilogue 2: fp16 transpose via smem bounce ----
    __syncthreads();
    unsigned short* Th = (unsigned short*)(smbuf);
#pragma unroll
    for (int ng = 0; ng < 8; ng++) {
        int col = ng * 8 + 2 * (l & 3);
#pragma unroll
        for (int v = 0; v < 4; v++) {
            int cc = col + (v & 1);
            int node = (v < 2) ? r0 : r1;
            u32 p = packh2(acc[ng][v], 0.f);
            Th[cc * TPAD + node] = (unsigned short)(p & 0xffffu);
        }
    }
    __syncthreads();

    const int b = m0 >> 10;
    const int node0 = m0 & (NT - 1);
    const size_t gbase = ((size_t)((h * BATCH + b) * 64)) * NT + node0;
    {
        int c = tid >> 2;
#pragma unroll
        for (int i = 0; i < 4; i++) {
            int nch = (tid & 3) + 4 * i;
            uint4 vh = *(const uint4*)(Th + c * TPAD + nch * 8);
            *(uint4*)(hT + gbase + (size_t)c * NT + nch * 8) = vh;
        }
    }
}

// ---------------- layers 2-3 GEMM: all-fp16 operands, cp.async pipeline ----
// X pre-split hi/lo planes [b][node][K], W pre-converted fp16. 2 MMA passes.
#define GH_BUF   40960                      // Xh 16K + Xl 16K + W 8K
#define GH_SMEM  (2 * GH_BUF)
__global__ __launch_bounds__(256) void gemm_h16(
    const __half* __restrict__ Xh, const __half* __restrict__ Xl,
    const __half* __restrict__ Wh,
    const float* __restrict__ a_src, const float* __restrict__ a_dst,
    float4* __restrict__ spk, float4* __restrict__ dpk,
    __half* __restrict__ hT, int K)
{
    extern __shared__ __align__(128) char smem[];
    const u32 sb = smem_u32(smem);

    const int tid = threadIdx.x;
    const int w = tid >> 5, l = tid & 31;
    const int h = blockIdx.y;
    const int m0 = blockIdx.x * 128, n0 = h * 64;

    float acc[8][4];
#pragma unroll
    for (int ng = 0; ng < 8; ng++)
#pragma unroll
        for (int r = 0; r < 4; r++) acc[ng][r] = 0.f;

    const int arow = w * 16 + (l & 7) + ((l >> 3) & 1) * 8;
    const int akh  = (l >> 4);
    const int sub = l >> 3;
    const int brow = (l & 7) + ((sub >> 1) << 3);

    const int nIter = K / 64;

    auto issue = [&](int t) {
        int k0 = t * 64;
        u32 base = sb + (t & 1) * GH_BUF;
#pragma unroll
        for (int i = 0; i < 4; i++) {
            int c = tid + i * 256;
            int row = c >> 3, kg = c & 7;
            u32 off = swzf((u32)(row * 128 + kg * 16));
            cpasync16(base + off,         Xh + (size_t)(m0 + row) * K + k0 + kg * 8);
            cpasync16(base + 16384 + off, Xl + (size_t)(m0 + row) * K + k0 + kg * 8);
        }
#pragma unroll
        for (int i = 0; i < 2; i++) {
            int c = tid + i * 256;
            int row = c >> 3, kg = c & 7;
            u32 off = swzf((u32)(row * 128 + kg * 16));
            cpasync16(base + 32768 + off, Wh + (size_t)(n0 + row) * K + k0 + kg * 8);
        }
        CP_COMMIT();
    };

    issue(0);

    for (int t = 0; t < nIter; t++) {
        CP_WAIT0();
        __syncthreads();
        if (t + 1 < nIter) issue(t + 1);

        u32 base = sb + (t & 1) * GH_BUF;
#pragma unroll
        for (int q = 0; q < 4; q++) {
            u32 ah[4], al[4];
            u32 aoff = swzf((u32)(arow * 128 + q * 32 + akh * 16));
            ldsm4(ah, base + aoff);
            ldsm4(al, base + 16384 + aoff);
            const int bchunk = 2 * q + (sub & 1);
            u32 bh[16];
#pragma unroll
            for (int g = 0; g < 4; g++) {
                u32 off = swzf((u32)((g * 16 + brow) * 128 + bchunk * 16));
                ldsm4(bh + g * 4, base + 32768 + off);
            }
#pragma unroll
            for (int g = 0; g < 4; g++) {
#pragma unroll
                for (int m = 0; m < 2; m++) {
                    int ng = g * 2 + m;
                    u32 b0 = bh[g * 4 + 2 * m], b1 = bh[g * 4 + 2 * m + 1];
                    mmaf16(acc[ng], ah, b0, b1);
                    mmaf16(acc[ng], al, b0, b1);
                }
            }
        }
        __syncthreads();
    }

    const int r0 = w * 16 + (l >> 2);
    const int r1 = r0 + 8;

    // ---- epilogue 1: attention scores ----
    {
        float s0 = 0.f, d0 = 0.f, s1 = 0.f, d1 = 0.f;
#pragma unroll
        for (int ng = 0; ng < 8; ng++) {
            int col = ng * 8 + 2 * (l & 3);
            float2 av = *(const float2*)(a_src + n0 + col);
            float2 dv = *(const float2*)(a_dst + n0 + col);
            s0 += acc[ng][0] * av.x + acc[ng][1] * av.y;
            d0 += acc[ng][0] * dv.x + acc[ng][1] * dv.y;
            s1 += acc[ng][2] * av.x + acc[ng][3] * av.y;
            d1 += acc[ng][2] * dv.x + acc[ng][3] * dv.y;
        }
        s0 += __shfl_xor_sync(0xffffffffu, s0, 1);
        s0 += __shfl_xor_sync(0xffffffffu, s0, 2);
        d0 += __shfl_xor_sync(0xffffffffu, d0, 1);
        d0 += __shfl_xor_sync(0xffffffffu, d0, 2);
        s1 += __shfl_xor_sync(0xffffffffu, s1, 1);
        s1 += __shfl_xor_sync(0xffffffffu, s1, 2);
        d1 += __shfl_xor_sync(0xffffffffu, d1, 1);
        d1 += __shfl_xor_sync(0xffffffffu, d1, 2);
        if ((l & 3) == 0) {
            int idx0 = h * (BATCH * NT) + m0 + r0;
            int idx1 = h * (BATCH * NT) + m0 + r1;
            spk[idx0] = make_float4(s0, __expf(s0), __expf(0.2f * s0), 0.f);
            dpk[idx0] = make_float4(d0, __expf(d0), __expf(0.2f * d0), 0.f);
            spk[idx1] = make_float4(s1, __expf(s1), __expf(0.2f * s1), 0.f);
            dpk[idx1] = make_float4(d1, __expf(d1), __expf(0.2f * d1), 0.f);
        }
    }

    // ---- epilogue 2: fp16 transpose via smem bounce ----
    __syncthreads();
    unsigned short* Th = (unsigned short*)smem;
#pragma unroll
    for (int ng = 0; ng < 8; ng++) {
        int col = ng * 8 + 2 * (l & 3);
#pragma unroll
        for (int v = 0; v < 4; v++) {
            int cc = col + (v & 1);
            int node = (v < 2) ? r0 : r1;
            u32 p = packh2(acc[ng][v], 0.f);
            Th[cc * TPAD + node] = (unsigned short)(p & 0xffffu);
        }
    }
    __syncthreads();

    const int b = m0 >> 10;
    const int node0 = m0 & (NT - 1);
    const size_t gbase = ((size_t)((h * BATCH + b) * 64)) * NT + node0;
    {
        int c = tid >> 2;
#pragma unroll
        for (int i = 0; i < 4; i++) {
            int nch = (tid & 3) + 4 * i;
            uint4 vh = *(const uint4*)(Th + c * TPAD + nch * 8);
            *(uint4*)(hT + gbase + (size_t)c * NT + nch * 8) = vh;
        }
    }
}

// ---------------- HMMA aggregation (fp16 single-pass) ----------------------
// Epilogue writes either f32 (layer 3, for readout) or pre-split fp16 hi/lo
// planes (layers 1-2, consumed by gemm_h16's cp.async staging).
__global__ __launch_bounds__(256, 2) void agg_mma_kernel(
    const __half* __restrict__ hTA,
    const float4* __restrict__ spkA, const float4* __restrict__ dpkA,
    const ull* __restrict__ bits64,
    const float* __restrict__ bias,
    __half* __restrict__ xhi, __half* __restrict__ xlo,
    float* __restrict__ xoutf, int wf32, int H)
{
    __shared__ __align__(16) __half sh_h[2][64 * 64];
    __shared__ __align__(16) float4 sh_sp[2][64];

    const int tid = threadIdx.x;
    const int w = tid >> 5, l = tid & 31;
    const int b = blockIdx.z, h = blockIdx.y;
    const int i0 = blockIdx.x * 128;
    const int hb = h * BATCH + b;
    const int fs = H * 64;

    const int r0 = w * 16 + (l >> 2);
    const int r1 = r0 + 8;
    const float4 dp0 = dpkA[hb * NT + i0 + r0];
    const float4 dp1 = dpkA[hb * NT + i0 + r1];
    const ull* mrow0 = bits64 + (size_t)(b * NT + i0 + r0) * 16;
    const ull* mrow1 = bits64 + (size_t)(b * NT + i0 + r1) * 16;

    const float4* spkp = spkA + hb * NT;
    const __half* hhp = hTA + (size_t)hb * 64 * NT;

    const int c0 = tid >> 3, jc = tid & 7;
    const u32 st0 = swzf((u32)(c0 * 128 + jc * 16));
    const u32 st1 = swzf((u32)((c0 + 32) * 128 + jc * 16));

    float acc[8][4];
#pragma unroll
    for (int ng = 0; ng < 8; ng++)
#pragma unroll
        for (int r = 0; r < 4; r++) acc[ng][r] = 0.f;
    float accrs[4] = {0.f, 0.f, 0.f, 0.f};

    uint4 pvh0, pvh1;
    float4 psc = make_float4(0.f, 0.f, 0.f, 0.f);

    auto ldg_tile = [&](int t) {
        int j0 = t * 64;
        pvh0 = *(const uint4*)(hhp + (size_t)c0 * NT + j0 + jc * 8);
        pvh1 = *(const uint4*)(hhp + (size_t)(c0 + 32) * NT + j0 + jc * 8);
        if (tid < 64) psc = spkp[j0 + tid];
    };

    ldg_tile(0);

    const u32 su[2] = { smem_u32(sh_h[0]), smem_u32(sh_h[1]) };

    const int sub = l >> 3;
    const int brow = (l & 7) + ((sub >> 1) << 3);

    for (int t = 0; t < 16; t++) {
        int buf = t & 1;
        *(uint4*)((char*)sh_h[buf] + st0) = pvh0;
        *(uint4*)((char*)sh_h[buf] + st1) = pvh1;
        if (tid < 64) sh_sp[buf][tid] = psc;
        __syncthreads();
        if (t < 15) ldg_tile(t + 1);

        const float4* sp = sh_sp[buf];
        const ull m0 = mrow0[t];
        const ull m1 = mrow1[t];

#pragma unroll
        for (int q = 0; q < 4; q++) {
            const int jA = q * 16 + 2 * (l & 3);
            float4 p0 = sp[jA], p1 = sp[jA + 1], p2 = sp[jA + 8], p3 = sp[jA + 9];

            u32 ahi[4];
            {
                float eA = edgef(p0, dp0, (u32)(m0 >> jA) & 1u);
                float eB = edgef(p1, dp0, (u32)(m0 >> (jA + 1)) & 1u);
                float eC = edgef(p2, dp0, (u32)(m0 >> (jA + 8)) & 1u);
                float eD = edgef(p3, dp0, (u32)(m0 >> (jA + 9)) & 1u);
                ahi[0] = packh2(eA, eB);
                ahi[2] = packh2(eC, eD);
            }
            {
                float eA = edgef(p0, dp1, (u32)(m1 >> jA) & 1u);
                float eB = edgef(p1, dp1, (u32)(m1 >> (jA + 1)) & 1u);
                float eC = edgef(p2, dp1, (u32)(m1 >> (jA + 8)) & 1u);
                float eD = edgef(p3, dp1, (u32)(m1 >> (jA + 9)) & 1u);
                ahi[1] = packh2(eA, eB);
                ahi[3] = packh2(eC, eD);
            }

            mmaf16(accrs, ahi, ONESH, ONESH);

            u32 bh[16];
            const int bchunk = 2 * q + (sub & 1);
#pragma unroll
            for (int g = 0; g < 4; g++) {
                u32 off = swzf((u32)((g * 16 + brow) * 128 + bchunk * 16));
                ldsm4(bh + g * 4, su[buf] + off);
            }
#pragma unroll
            for (int g = 0; g < 4; g++) {
#pragma unroll
                for (int m = 0; m < 2; m++) {
                    int ng = g * 2 + m;
                    mmaf16(acc[ng], ahi, bh[g * 4 + 2 * m], bh[g * 4 + 2 * m + 1]);
                }
            }
        }
        __syncthreads();
    }

    float rinv0 = 1.0f / accrs[0];
    float rinv1 = 1.0f / accrs[2];

    const size_t ro0 = (size_t)(b * NT + i0 + r0) * fs + h * 64;
    const size_t ro1 = (size_t)(b * NT + i0 + r1) * fs + h * 64;
#pragma unroll
    for (int ng = 0; ng < 8; ng++) {
        int col = ng * 8 + 2 * (l & 3);
        float2 bb = *(const float2*)(bias + h * 64 + col);
        float2 o0, o1;
        o0.x = fmaxf(acc[ng][0] * rinv0 + bb.x, 0.f);
        o0.y = fmaxf(acc[ng][1] * rinv0 + bb.y, 0.f);
        o1.x = fmaxf(acc[ng][2] * rinv1 + bb.x, 0.f);
        o1.y = fmaxf(acc[ng][3] * rinv1 + bb.y, 0.f);
        if (wf32) {
            *(float2*)(xoutf + ro0 + col) = o0;
            *(float2*)(xoutf + ro1 + col) = o1;
        } else {
            u32 ph, pl;
            split2h(o0.x, o0.y, ph, pl);
            *(u32*)(xhi + ro0 + col) = ph;
            *(u32*)(xlo + ro0 + col) = pl;
            split2h(o1.x, o1.y, ph, pl);
            *(u32*)(xhi + ro1 + col) = ph;
            *(u32*)(xlo + ro1 + col) = pl;
        }
    }
}

// ---------------- readout --------------------------------------------------
__global__ void gsum_kernel(const float* __restrict__ x, float* __restrict__ g) {
    int b = blockIdx.x;
    int tid = threadIdx.x;
    int c = tid & 63, nq = tid >> 6;
    float acc = 0.f;
    for (int n = nq; n < NT; n += 4) acc += x[((size_t)b * NT + n) * 64 + c];
    __shared__ float sm[256];
    sm[tid] = acc;
    __syncthreads();
    if (tid < 64) g[b * 64 + tid] = sm[tid] + sm[64 + tid] + sm[128 + tid] + sm[192 + tid];
}

__global__ void z2_kernel(const float* __restrict__ g, const float* __restrict__ wg,
                          const float* __restrict__ bg, const float* __restrict__ wv,
                          float* __restrict__ z2) {
    int b = blockIdx.x;
    int c = threadIdx.x;
    float acc = bg[c];
    for (int k = 0; k < 64; k++) acc += g[b * 64 + k] * wg[c * 64 + k];
    float y = fmaxf(acc, 0.f) * wv[64 + c];
    __shared__ float sm[64];
    sm[c] = y;
    __syncthreads();
    if (c == 0) {
        float t = 0.f;
        for (int k = 0; k < 64; k++) t += sm[k];
        z2[b] = t;
    }
}

__global__ __launch_bounds__(256) void final_kernel(
    const float* __restrict__ x,
    const float* __restrict__ wn, const float* __restrict__ bn,
    const float* __restrict__ wv, const float* __restrict__ bv,
    const float* __restrict__ z2, float* __restrict__ out)
{
    __shared__ float wns[64][65];
    __shared__ float bns[64], wvs[64];
    int tid = threadIdx.x;
#pragma unroll
    for (int l = 0; l < 16; l++) {
        int f = tid + l * 256;
        wns[f >> 6][f & 63] = wn[f];
    }
    if (tid < 64) { bns[tid] = bn[tid]; wvs[tid] = wv[tid]; }
    __syncthreads();

    int row = blockIdx.x * 64 + (tid >> 2);
    int q = tid & 3;
    float xr[64];
#pragma unroll
    for (int k = 0; k < 64; k++) xr[k] = x[(size_t)row * 64 + k];
    float y = 0.f;
    for (int c16 = 0; c16 < 16; c16++) {
        int c = q * 16 + c16;
        float acc = bns[c];
#pragma unroll
        for (int k = 0; k < 64; k++) acc += xr[k] * wns[c][k];
        y += fmaxf(acc, 0.f) * wvs[c];
    }
    y += __shfl_xor_sync(0xffffffffu, y, 1);
    y += __shfl_xor_sync(0xffffffffu, y, 2);
    if (q == 0) out[row] = y + z2[row >> 10] + bv[0];
}

// ---------------- launch ----------------------------------------------------
extern "C" void kernel_launch(void* const* d_in, const int* in_sizes, int n_in,
                              void* d_out, int out_size)
{
    const float* xin = (const float*)d_in[0];
    const int*   adj = (const int*)d_in[1];
    const float* w1  = (const float*)d_in[2];
    const float* as1 = (const float*)d_in[3];
    const float* ad1 = (const float*)d_in[4];
    const float* b1  = (const float*)d_in[5];
    const float* w2  = (const float*)d_in[6];
    const float* as2 = (const float*)d_in[7];
    const float* ad2 = (const float*)d_in[8];
    const float* b2  = (const float*)d_in[9];
    const float* w3  = (const float*)d_in[10];
    const float* as3 = (const float*)d_in[11];
    const float* ad3 = (const float*)d_in[12];
    const float* b3  = (const float*)d_in[13];
    const float* wn  = (const float*)d_in[14];
    const float* bn  = (const float*)d_in[15];
    const float* wg  = (const float*)d_in[16];
    const float* bg  = (const float*)d_in[17];
    const float* wv  = (const float*)d_in[18];
    const float* bv  = (const float*)d_in[19];
    float* out = (float*)d_out;

    float *bufB, *gsm, *z2p;
    float4 *spk, *dpk;
    __half *hT, *xhi, *xlo, *w2h, *w3h;
    u32* bits;
    cudaGetSymbolAddress((void**)&bufB, g_bufB);
    cudaGetSymbolAddress((void**)&spk,  g_spk);
    cudaGetSymbolAddress((void**)&dpk,  g_dpk);
    cudaGetSymbolAddress((void**)&hT,   g_hT);
    cudaGetSymbolAddress((void**)&xhi,  g_xhi);
    cudaGetSymbolAddress((void**)&xlo,  g_xlo);
    cudaGetSymbolAddress((void**)&w2h,  g_w2h);
    cudaGetSymbolAddress((void**)&w3h,  g_w3h);
    cudaGetSymbolAddress((void**)&bits, g_bits);
    cudaGetSymbolAddress((void**)&gsm,  g_gsum);
    cudaGetSymbolAddress((void**)&z2p,  g_z2);

    cudaFuncSetAttribute(gemm_h16, cudaFuncAttributeMaxDynamicSharedMemorySize, GH_SMEM);

    const int M = BATCH * NT;
    const ull* bits64 = (const ull*)bits;

    pack_adj_kernel<<<M, 32>>>(adj, bits);
    convh_kernel<<<(256 * 256 / 4 + 255) / 256, 256>>>(w2, w2h, 256 * 256 / 4);
    convh_kernel<<<(64 * 256 / 4 + 255) / 256, 256>>>(w3, w3h, 64 * 256 / 4);

    // layer 1: 64 -> 4x64 (f32-input gemm + scores + fp16 transpose)
    gemm_fused<<<dim3(M / 128, 4), 256>>>(xin, w1, as1, ad1, spk, dpk, hT, 64);
    agg_mma_kernel<<<dim3(NT / 128, 4, BATCH), 256>>>(
        hT, spk, dpk, bits64, b1, xhi, xlo, nullptr, 0, 4);

    // layer 2: 4x64 -> 4x64 (all-fp16 pipelined gemm)
    gemm_h16<<<dim3(M / 128, 4), 256, GH_SMEM>>>(xhi, xlo, w2h, as2, ad2,
                                                 spk, dpk, hT, 256);
    agg_mma_kernel<<<dim3(NT / 128, 4, BATCH), 256>>>(
        hT, spk, dpk, bits64, b2, xhi, xlo, nullptr, 0, 4);

    // layer 3: 4x64 -> 64 (H=1)
    gemm_h16<<<dim3(M / 128, 1), 256, GH_SMEM>>>(xhi, xlo, w3h, as3, ad3,
                                                 spk, dpk, hT, 256);
    agg_mma_kernel<<<dim3(NT / 128, 1, BATCH), 256>>>(
        hT, spk, dpk, bits64, b3, nullptr, nullptr, bufB, 1, 1);

    // readout
    gsum_kernel<<<BATCH, 256>>>(bufB, gsm);
    z2_kernel<<<BATCH, 64>>>(gsm, wg, bg, wv, z2p);
    final_kernel<<<M / 64, 256>>>(bufB, wn, bn, wv, bv, z2p, out);
}